// round 2
// baseline (speedup 1.0000x reference)
#include <cuda_runtime.h>

#define N_B 32
#define C_B 64
#define D_B 128
#define MAT (D_B*D_B)          // 16384
#define STR 132                // padded smem row stride (floats)
#define SMEM3 (3*D_B*STR*4)    // 202752 bytes dynamic smem for k_attn
#define TPB 512

typedef unsigned long long u64;

// ---------------- scratch (device globals; no allocations allowed) ----------
__device__ float g_rv[N_B*C_B*D_B];   // rsqrt(max(|diag|,1e-4)) per (n,c,i)
__device__ float g_XQ[N_B*C_B*MAT];   // X mixed by w_queries
__device__ float g_XK[N_B*C_B*MAT];   // X mixed by w_keys

// ---------------- packed f32x2 helpers (2x fp32 FMA throughput) -------------
__device__ __forceinline__ u64 bcast2(float x){
    u64 r; unsigned xi = __float_as_uint(x);
    asm("mov.b64 %0, {%1, %1};" : "=l"(r) : "r"(xi));
    return r;
}
__device__ __forceinline__ u64 ffma2(u64 a, u64 b, u64 c){
    u64 d;
    asm("fma.rn.f32x2 %0, %1, %2, %3;" : "=l"(d) : "l"(a), "l"(b), "l"(c));
    return d;
}
__device__ __forceinline__ void unpack2(u64 v, float& lo, float& hi){
    unsigned a, b;
    asm("mov.b64 {%0, %1}, %2;" : "=r"(a), "=r"(b) : "l"(v));
    lo = __uint_as_float(a); hi = __uint_as_float(b);
}
union F4U { float4 f; u64 u[2]; };

__device__ __forceinline__ float clip1(float x){
    return fminf(1.f, fmaxf(-1.f, x));
}

// ============================================================================
// Kernel 0: per-(n,c) diagonal rsqrt factors
// ============================================================================
__global__ void k_rinv(const float* __restrict__ in){
    int nk = blockIdx.x;            // n*C + c
    int t  = threadIdx.x;           // 0..127
    float v = in[(size_t)nk*MAT + t*D_B + t];
    g_rv[nk*D_B + t] = rsqrtf(fmaxf(fabsf(v), 1e-4f));
}

// ============================================================================
// Kernel 1: fused cov2cor + channel mixing.
//   X[n,c,i,j] = clip(in * rv_i * rv_j);  XWQ/XWK = einsum('ncij,ck->nkij')
// grid (D_B, N_B): block handles row i = blockIdx.x (128 j's), all 64 k.
// ============================================================================
__global__ __launch_bounds__(256, 1) void k_mix(const float* __restrict__ inp,
                                                const float* __restrict__ wq,
                                                const float* __restrict__ wk){
    __shared__ float sWQ[C_B*C_B];
    __shared__ float sWK[C_B*C_B];
    __shared__ float sX [8*D_B];
    __shared__ float sRV[8*D_B];
    int tid = threadIdx.x;
    int n   = blockIdx.y;
    int irow= blockIdx.x;               // ij0 = irow*128, j = 0..127
    for (int i = tid; i < C_B*C_B; i += 256){ sWQ[i] = wq[i]; sWK[i] = wk[i]; }
    int tx = tid & 31;           // j sub-tile: j = tx*4 + p
    int ty = tid >> 5;           // k sub-tile
    int k0 = ty * 8;
    u64 aQ[4][4], aK[4][4];
    #pragma unroll
    for (int p = 0; p < 4; p++)
        #pragma unroll
        for (int q = 0; q < 4; q++){ aQ[p][q] = 0ull; aK[p][q] = 0ull; }
    __syncthreads();
    for (int cc = 0; cc < C_B; cc += 8){
        {   // stage rinv rows for these 8 channels (g_rv is tiny -> L2-hot)
            int idx = tid * 4;           // 256*4 = 1024 floats
            int cl = idx >> 7, j = idx & 127;
            *(float4*)&sRV[idx] = *(const float4*)&g_rv[((size_t)(n*C_B + cc + cl))*D_B + j];
        }
        __syncthreads();
        {   // stage 8 channels x 128 j of X = clip(cov2cor)
            int cl = tid >> 5, jj = (tid & 31) * 4;
            float4 v = *(const float4*)&inp[((size_t)(n*C_B + cc + cl))*MAT + irow*D_B + jj];
            float ri = sRV[cl*D_B + irow];
            v.x = clip1(v.x * ri * sRV[cl*D_B + jj+0]);
            v.y = clip1(v.y * ri * sRV[cl*D_B + jj+1]);
            v.z = clip1(v.z * ri * sRV[cl*D_B + jj+2]);
            v.w = clip1(v.w * ri * sRV[cl*D_B + jj+3]);
            *(float4*)&sX[cl*D_B + jj] = v;
        }
        __syncthreads();
        #pragma unroll
        for (int cl = 0; cl < 8; cl++){
            int c = cc + cl;
            float4 xv = *(const float4*)&sX[cl*D_B + tx*4];
            u64 xx[4] = { bcast2(xv.x), bcast2(xv.y), bcast2(xv.z), bcast2(xv.w) };
            F4U q0, q1, kk0, kk1;
            q0.f  = *(const float4*)&sWQ[c*C_B + k0];
            q1.f  = *(const float4*)&sWQ[c*C_B + k0 + 4];
            kk0.f = *(const float4*)&sWK[c*C_B + k0];
            kk1.f = *(const float4*)&sWK[c*C_B + k0 + 4];
            u64 bq[4] = { q0.u[0],  q0.u[1],  q1.u[0],  q1.u[1]  };
            u64 bk[4] = { kk0.u[0], kk0.u[1], kk1.u[0], kk1.u[1] };
            #pragma unroll
            for (int p = 0; p < 4; p++){
                #pragma unroll
                for (int q = 0; q < 4; q++){
                    aQ[p][q] = ffma2(xx[p], bq[q], aQ[p][q]);
                    aK[p][q] = ffma2(xx[p], bk[q], aK[p][q]);
                }
            }
        }
        __syncthreads();
    }
    #pragma unroll
    for (int q = 0; q < 4; q++){
        #pragma unroll
        for (int h = 0; h < 2; h++){
            int k = k0 + q*2 + h;
            float vq[4], vk[4];
            #pragma unroll
            for (int p = 0; p < 4; p++){
                float lo, hi;
                unpack2(aQ[p][q], lo, hi); vq[p] = h ? hi : lo;
                unpack2(aK[p][q], lo, hi); vk[p] = h ? hi : lo;
            }
            size_t base = ((size_t)(n*C_B + k))*MAT + irow*D_B + tx*4;
            *(float4*)&g_XQ[base] = make_float4(vq[0], vq[1], vq[2], vq[3]);
            *(float4*)&g_XK[base] = make_float4(vk[0], vk[1], vk[2], vk[3]);
        }
    }
}

// ============================================================================
// Kernel 2 helpers: smem-resident 128x128x128 matmuls, 512 threads,
// thread computes a 4x8 output tile as 4x4 f32x2 accumulators.
// ============================================================================
__device__ __forceinline__ void load_tile(float* dst, const float* __restrict__ src, int tid){
    #pragma unroll
    for (int e = tid; e < MAT/4; e += TPB){
        int i = e >> 5, j = (e & 31) * 4;
        *(float4*)&dst[i*STR + j] = *(const float4*)&src[e*4];
    }
}

// X tile: clip(inp * rv_i * rv_j), cov2cor fused
__device__ __forceinline__ void load_X(float* dst, const float* __restrict__ src,
                                       const float* __restrict__ rv, int tid){
    #pragma unroll
    for (int e = tid; e < MAT/4; e += TPB){
        int i = e >> 5, j = (e & 31) * 4;
        float4 v = *(const float4*)&src[e*4];
        float ri = rv[i];
        v.x = clip1(v.x * ri * rv[j+0]);
        v.y = clip1(v.y * ri * rv[j+1]);
        v.z = clip1(v.z * ri * rv[j+2]);
        v.w = clip1(v.w * ri * rv[j+3]);
        *(float4*)&dst[i*STR + j] = v;
    }
}

// C[i][j] = sum_m A[m][i] * B[m][j]
__device__ __forceinline__ void mm_atb(float* __restrict__ C, const float* __restrict__ A,
                                       const float* __restrict__ B, int tid){
    int tx = tid & 15, ty = tid >> 4;   // ty in 0..31
    int i0 = ty*4, j0 = tx*8;
    u64 acc[4][4];
    #pragma unroll
    for (int p = 0; p < 4; p++)
        #pragma unroll
        for (int q = 0; q < 4; q++) acc[p][q] = 0ull;
    #pragma unroll 4
    for (int m = 0; m < D_B; m++){
        float4 a0 = *(const float4*)&A[m*STR + i0];
        F4U b0v, b1v;
        b0v.f = *(const float4*)&B[m*STR + j0];
        b1v.f = *(const float4*)&B[m*STR + j0 + 4];
        u64 bb[4] = { b0v.u[0], b0v.u[1], b1v.u[0], b1v.u[1] };
        float av[4] = { a0.x, a0.y, a0.z, a0.w };
        #pragma unroll
        for (int p = 0; p < 4; p++){
            u64 ap = bcast2(av[p]);
            #pragma unroll
            for (int q = 0; q < 4; q++) acc[p][q] = ffma2(ap, bb[q], acc[p][q]);
        }
    }
    #pragma unroll
    for (int p = 0; p < 4; p++){
        F4U o0, o1;
        o0.u[0] = acc[p][0]; o0.u[1] = acc[p][1];
        o1.u[0] = acc[p][2]; o1.u[1] = acc[p][3];
        *(float4*)&C[(i0+p)*STR + j0]     = o0.f;
        *(float4*)&C[(i0+p)*STR + j0 + 4] = o1.f;
    }
}

// C[i][j] = sum_m A[i][m] * B[m][j]
__device__ __forceinline__ void mm_ab(float* __restrict__ C, const float* __restrict__ A,
                                      const float* __restrict__ B, int tid){
    int tx = tid & 15, ty = tid >> 4;
    int i0 = ty*4, j0 = tx*8;
    u64 acc[4][4];
    #pragma unroll
    for (int p = 0; p < 4; p++)
        #pragma unroll
        for (int q = 0; q < 4; q++) acc[p][q] = 0ull;
    for (int m = 0; m < D_B; m += 4){
        float4 a4[4];
        #pragma unroll
        for (int p = 0; p < 4; p++) a4[p] = *(const float4*)&A[(i0+p)*STR + m];
        #pragma unroll
        for (int s = 0; s < 4; s++){
            F4U b0v, b1v;
            b0v.f = *(const float4*)&B[(m+s)*STR + j0];
            b1v.f = *(const float4*)&B[(m+s)*STR + j0 + 4];
            u64 bb[4] = { b0v.u[0], b0v.u[1], b1v.u[0], b1v.u[1] };
            #pragma unroll
            for (int p = 0; p < 4; p++){
                float as = (s == 0) ? a4[p].x : (s == 1) ? a4[p].y
                         : (s == 2) ? a4[p].z : a4[p].w;
                u64 ap = bcast2(as);
                #pragma unroll
                for (int q = 0; q < 4; q++) acc[p][q] = ffma2(ap, bb[q], acc[p][q]);
            }
        }
    }
    #pragma unroll
    for (int p = 0; p < 4; p++){
        F4U o0, o1;
        o0.u[0] = acc[p][0]; o0.u[1] = acc[p][1];
        o1.u[0] = acc[p][2]; o1.u[1] = acc[p][3];
        *(float4*)&C[(i0+p)*STR + j0]     = o0.f;
        *(float4*)&C[(i0+p)*STR + j0 + 4] = o1.f;
    }
}

// out = inputs + lam * (A * B), streamed to gmem
__device__ __forceinline__ void mm_ab_out(const float* __restrict__ A, const float* __restrict__ B,
                                          const float* __restrict__ inp, float* __restrict__ out,
                                          float lam, int tid){
    int tx = tid & 15, ty = tid >> 4;
    int i0 = ty*4, j0 = tx*8;
    u64 acc[4][4];
    #pragma unroll
    for (int p = 0; p < 4; p++)
        #pragma unroll
        for (int q = 0; q < 4; q++) acc[p][q] = 0ull;
    for (int m = 0; m < D_B; m += 4){
        float4 a4[4];
        #pragma unroll
        for (int p = 0; p < 4; p++) a4[p] = *(const float4*)&A[(i0+p)*STR + m];
        #pragma unroll
        for (int s = 0; s < 4; s++){
            F4U b0v, b1v;
            b0v.f = *(const float4*)&B[(m+s)*STR + j0];
            b1v.f = *(const float4*)&B[(m+s)*STR + j0 + 4];
            u64 bb[4] = { b0v.u[0], b0v.u[1], b1v.u[0], b1v.u[1] };
            #pragma unroll
            for (int p = 0; p < 4; p++){
                float as = (s == 0) ? a4[p].x : (s == 1) ? a4[p].y
                         : (s == 2) ? a4[p].z : a4[p].w;
                u64 ap = bcast2(as);
                #pragma unroll
                for (int q = 0; q < 4; q++) acc[p][q] = ffma2(ap, bb[q], acc[p][q]);
            }
        }
    }
    #pragma unroll
    for (int p = 0; p < 4; p++){
        int row = i0 + p;
        float4 iv0 = *(const float4*)&inp[row*D_B + j0];
        float4 iv1 = *(const float4*)&inp[row*D_B + j0 + 4];
        float r[8];
        unpack2(acc[p][0], r[0], r[1]); unpack2(acc[p][1], r[2], r[3]);
        unpack2(acc[p][2], r[4], r[5]); unpack2(acc[p][3], r[6], r[7]);
        float4 o0 = make_float4(iv0.x + lam*r[0], iv0.y + lam*r[1],
                                iv0.z + lam*r[2], iv0.w + lam*r[3]);
        float4 o1 = make_float4(iv1.x + lam*r[4], iv1.y + lam*r[5],
                                iv1.z + lam*r[6], iv1.w + lam*r[7]);
        *(float4*)&out[row*D_B + j0]     = o0;
        *(float4*)&out[row*D_B + j0 + 4] = o1;
    }
}

// soft_pd_max, in place on smem tile M (stride STR). Ends synced.
__device__ __forceinline__ void soft_pd(float* M, int tid, float* s_dia,
                                        float* s_rinv, float* s_red,
                                        float* s_bmax, float* s_tot){
    float mx = -3.4e38f;
    #pragma unroll
    for (int e = tid; e < MAT/4; e += TPB){
        int i = e >> 5, j = (e & 31) * 4;
        float4 v = *(const float4*)&M[i*STR + j];
        mx = fmaxf(mx, fmaxf(fmaxf(v.x, v.y), fmaxf(v.z, v.w)));
    }
    #pragma unroll
    for (int o = 16; o; o >>= 1) mx = fmaxf(mx, __shfl_xor_sync(0xffffffffu, mx, o));
    if ((tid & 31) == 0) s_red[tid >> 5] = mx;
    __syncthreads();
    if (tid == 0){
        float m2 = s_red[0];
        #pragma unroll
        for (int w = 1; w < TPB/32; w++) m2 = fmaxf(m2, s_red[w]);
        *s_bmax = m2;
    }
    __syncthreads();
    float bmax = *s_bmax;
    #pragma unroll
    for (int e = tid; e < MAT/4; e += TPB){
        int i = e >> 5, j = (e & 31) * 4;
        float4 v = *(float4*)&M[i*STR + j];
        v.x = __expf(v.x - bmax); v.y = __expf(v.y - bmax);
        v.z = __expf(v.z - bmax); v.w = __expf(v.w - bmax);
        *(float4*)&M[i*STR + j] = v;
    }
    __syncthreads();
    if (tid < D_B){
        const float* r = M + tid*STR;
        float s = 0.f;
        #pragma unroll
        for (int j4 = 0; j4 < D_B/4; j4++){
            float4 v = *(const float4*)&r[j4*4];
            s += (v.x + v.y) + (v.z + v.w);
        }
        s_dia[tid] = s;
    }
    __syncthreads();
    if (tid < 32){
        float t = s_dia[tid] + s_dia[tid+32] + s_dia[tid+64] + s_dia[tid+96];
        #pragma unroll
        for (int o = 16; o; o >>= 1) t += __shfl_xor_sync(0xffffffffu, t, o);
        if (tid == 0) *s_tot = t;
    }
    __syncthreads();
    if (tid < D_B){
        float total = *s_tot;
        float d = fmaxf(fmaxf(s_dia[tid], total / 100000.0f), 1e-5f);
        s_rinv[tid] = rsqrtf(d);
    }
    __syncthreads();
    #pragma unroll
    for (int e = tid; e < MAT/4; e += TPB){
        int i = e >> 5, j = (e & 31) * 4;
        float ri = s_rinv[i];
        float4 v = *(float4*)&M[i*STR + j];
        v.x *= ri * s_rinv[j];   v.y *= ri * s_rinv[j+1];
        v.z *= ri * s_rinv[j+2]; v.w *= ri * s_rinv[j+3];
        *(float4*)&M[i*STR + j] = v;
    }
    __syncthreads();
}

// ============================================================================
// Kernel 2: per-(n,k) chain. A_pre = K^T Q K; A = soft_pd(A_pre);
//           out = inputs + lam * (A X A^T)
// ============================================================================
__global__ __launch_bounds__(TPB, 1) void k_attn(const float* __restrict__ inp,
                                                 const float* __restrict__ lam,
                                                 float* __restrict__ out){
    extern __shared__ float sm[];
    float* b0 = sm;                 // XWK -> X -> A^T
    float* b1 = sm +     D_B*STR;   // XWQ -> A_pre -> A
    float* b2 = sm + 2 * D_B*STR;   // St  -> P = A*X
    __shared__ float s_dia[D_B], s_rinvd[D_B], s_rv[D_B], s_red[TPB/32];
    __shared__ float s_bmax, s_tot;
    int tid = threadIdx.x;
    int nk  = blockIdx.x;
    size_t base = (size_t)nk * MAT;

    if (tid < D_B) s_rv[tid] = g_rv[nk*D_B + tid];
    load_tile(b0, g_XK + base, tid);
    load_tile(b1, g_XQ + base, tid);
    __syncthreads();
    mm_atb(b2, b1, b0, tid);        // St = Q^T K
    __syncthreads();
    mm_atb(b1, b2, b0, tid);        // A_pre = St^T K = K^T Q K
    __syncthreads();
    load_X(b0, inp + base, s_rv, tid);        // overlap gmem X load with soft_pd
    soft_pd(b1, tid, s_dia, s_rinvd, s_red, &s_bmax, &s_tot);  // b1 = A (ends synced)
    mm_ab(b2, b1, b0, tid);         // P = A X
    __syncthreads();
    for (int e = tid; e < MAT; e += TPB){     // b0 = A^T
        int i = e >> 7, j = e & 127;
        b0[j*STR + i] = b1[i*STR + j];
    }
    __syncthreads();
    mm_ab_out(b2, b0, inp + base, out + base, lam[nk & (C_B - 1)], tid);
}

// ============================================================================
extern "C" void kernel_launch(void* const* d_in, const int* in_sizes, int n_in,
                              void* d_out, int out_size){
    const float* inp = (const float*)d_in[0];
    const float* wq  = (const float*)d_in[1];
    const float* wk  = (const float*)d_in[2];
    const float* lam = (const float*)d_in[3];
    float* out = (float*)d_out;

    cudaFuncSetAttribute(k_attn, cudaFuncAttributeMaxDynamicSharedMemorySize, SMEM3);

    k_rinv<<<N_B*C_B, D_B>>>(inp);
    k_mix<<<dim3(D_B, N_B), 256>>>(inp, wq, wk);
    k_attn<<<N_B*C_B, TPB, SMEM3>>>(inp, lam, out);
}

// round 3
// speedup vs baseline: 1.3886x; 1.3886x over previous
#include <cuda_runtime.h>

#define N_B 32
#define C_B 64
#define D_B 128
#define MAT (D_B*D_B)          // 16384
#define STR 132                // padded smem row stride (floats)
#define SMEM3 (3*D_B*STR*4)    // 202752 bytes dynamic smem for k_attn
#define TPB 256

typedef unsigned long long u64;

// ---------------- scratch (device globals; no allocations allowed) ----------
__device__ float g_rv[N_B*C_B*D_B];   // rsqrt(max(|diag|,1e-4)) per (n,c,i)
__device__ float g_XQ[N_B*C_B*MAT];   // X mixed by w_queries
__device__ float g_XK[N_B*C_B*MAT];   // X mixed by w_keys

// ---------------- packed f32x2 helpers (2x fp32 FMA throughput) -------------
__device__ __forceinline__ u64 bcast2(float x){
    u64 r; unsigned xi = __float_as_uint(x);
    asm("mov.b64 %0, {%1, %1};" : "=l"(r) : "r"(xi));
    return r;
}
__device__ __forceinline__ u64 ffma2(u64 a, u64 b, u64 c){
    u64 d;
    asm("fma.rn.f32x2 %0, %1, %2, %3;" : "=l"(d) : "l"(a), "l"(b), "l"(c));
    return d;
}
__device__ __forceinline__ void unpack2(u64 v, float& lo, float& hi){
    unsigned a, b;
    asm("mov.b64 {%0, %1}, %2;" : "=r"(a), "=r"(b) : "l"(v));
    lo = __uint_as_float(a); hi = __uint_as_float(b);
}
union F4U { float4 f; u64 u[2]; };

__device__ __forceinline__ float clip1(float x){
    return fminf(1.f, fmaxf(-1.f, x));
}

// ============================================================================
// Kernel 0: per-(n,c) diagonal rsqrt factors
// ============================================================================
__global__ void k_rinv(const float* __restrict__ in){
    int nk = blockIdx.x;            // n*C + c
    int t  = threadIdx.x;           // 0..127
    float v = in[(size_t)nk*MAT + t*D_B + t];
    g_rv[nk*D_B + t] = rsqrtf(fmaxf(fabsf(v), 1e-4f));
}

// ============================================================================
// Kernel 1: fused cov2cor + channel mixing.
//   X[n,c,i,j] = clip(in * rv_i * rv_j);  XWQ/XWK = einsum('ncij,ck->nkij')
// grid (D_B, N_B): block handles row i = blockIdx.x (128 j's), all 64 k.
// ============================================================================
__global__ __launch_bounds__(256, 1) void k_mix(const float* __restrict__ inp,
                                                const float* __restrict__ wq,
                                                const float* __restrict__ wk){
    __shared__ float sWQ[C_B*C_B];
    __shared__ float sWK[C_B*C_B];
    __shared__ float sX [8*D_B];
    __shared__ float sRV[8*D_B];
    int tid = threadIdx.x;
    int n   = blockIdx.y;
    int irow= blockIdx.x;               // row i, j = 0..127
    for (int i = tid; i < C_B*C_B; i += 256){ sWQ[i] = wq[i]; sWK[i] = wk[i]; }
    int tx = tid & 31;           // j sub-tile: j = tx*4 + p
    int ty = tid >> 5;           // k sub-tile
    int k0 = ty * 8;
    u64 aQ[4][4], aK[4][4];
    #pragma unroll
    for (int p = 0; p < 4; p++)
        #pragma unroll
        for (int q = 0; q < 4; q++){ aQ[p][q] = 0ull; aK[p][q] = 0ull; }
    __syncthreads();
    for (int cc = 0; cc < C_B; cc += 8){
        {   // stage rinv rows for these 8 channels (g_rv is tiny -> L2-hot)
            int idx = tid * 4;           // 256*4 = 1024 floats
            int cl = idx >> 7, j = idx & 127;
            *(float4*)&sRV[idx] = *(const float4*)&g_rv[((size_t)(n*C_B + cc + cl))*D_B + j];
        }
        __syncthreads();
        {   // stage 8 channels x 128 j of X = clip(cov2cor)
            int cl = tid >> 5, jj = (tid & 31) * 4;
            float4 v = *(const float4*)&inp[((size_t)(n*C_B + cc + cl))*MAT + irow*D_B + jj];
            float ri = sRV[cl*D_B + irow];
            v.x = clip1(v.x * ri * sRV[cl*D_B + jj+0]);
            v.y = clip1(v.y * ri * sRV[cl*D_B + jj+1]);
            v.z = clip1(v.z * ri * sRV[cl*D_B + jj+2]);
            v.w = clip1(v.w * ri * sRV[cl*D_B + jj+3]);
            *(float4*)&sX[cl*D_B + jj] = v;
        }
        __syncthreads();
        #pragma unroll
        for (int cl = 0; cl < 8; cl++){
            int c = cc + cl;
            float4 xv = *(const float4*)&sX[cl*D_B + tx*4];
            u64 xx[4] = { bcast2(xv.x), bcast2(xv.y), bcast2(xv.z), bcast2(xv.w) };
            F4U q0, q1, kk0, kk1;
            q0.f  = *(const float4*)&sWQ[c*C_B + k0];
            q1.f  = *(const float4*)&sWQ[c*C_B + k0 + 4];
            kk0.f = *(const float4*)&sWK[c*C_B + k0];
            kk1.f = *(const float4*)&sWK[c*C_B + k0 + 4];
            u64 bq[4] = { q0.u[0],  q0.u[1],  q1.u[0],  q1.u[1]  };
            u64 bk[4] = { kk0.u[0], kk0.u[1], kk1.u[0], kk1.u[1] };
            #pragma unroll
            for (int p = 0; p < 4; p++){
                #pragma unroll
                for (int q = 0; q < 4; q++){
                    aQ[p][q] = ffma2(xx[p], bq[q], aQ[p][q]);
                    aK[p][q] = ffma2(xx[p], bk[q], aK[p][q]);
                }
            }
        }
        __syncthreads();
    }
    #pragma unroll
    for (int q = 0; q < 4; q++){
        #pragma unroll
        for (int h = 0; h < 2; h++){
            int k = k0 + q*2 + h;
            float vq[4], vk[4];
            #pragma unroll
            for (int p = 0; p < 4; p++){
                float lo, hi;
                unpack2(aQ[p][q], lo, hi); vq[p] = h ? hi : lo;
                unpack2(aK[p][q], lo, hi); vk[p] = h ? hi : lo;
            }
            size_t base = ((size_t)(n*C_B + k))*MAT + irow*D_B + tx*4;
            *(float4*)&g_XQ[base] = make_float4(vq[0], vq[1], vq[2], vq[3]);
            *(float4*)&g_XK[base] = make_float4(vk[0], vk[1], vk[2], vk[3]);
        }
    }
}

// ============================================================================
// Kernel 2 helpers: smem-resident 128x128x128 matmuls, 256 threads,
// thread computes an 8x8 output tile as 8x4 f32x2 accumulators.
// ============================================================================
__device__ __forceinline__ void load_tile(float* dst, const float* __restrict__ src, int tid){
    #pragma unroll
    for (int e = tid; e < MAT/4; e += TPB){
        int i = e >> 5, j = (e & 31) * 4;
        *(float4*)&dst[i*STR + j] = *(const float4*)&src[e*4];
    }
}

// X tile: clip(inp * rv_i * rv_j), cov2cor fused
__device__ __forceinline__ void load_X(float* dst, const float* __restrict__ src,
                                       const float* __restrict__ rv, int tid){
    #pragma unroll
    for (int e = tid; e < MAT/4; e += TPB){
        int i = e >> 5, j = (e & 31) * 4;
        float4 v = *(const float4*)&src[e*4];
        float ri = rv[i];
        v.x = clip1(v.x * ri * rv[j+0]);
        v.y = clip1(v.y * ri * rv[j+1]);
        v.z = clip1(v.z * ri * rv[j+2]);
        v.w = clip1(v.w * ri * rv[j+3]);
        *(float4*)&dst[i*STR + j] = v;
    }
}

// C[i][j] = sum_m A[m][i] * B[m][j]        (both operands read along rows)
__device__ __forceinline__ void mm_atb(float* __restrict__ C, const float* __restrict__ A,
                                       const float* __restrict__ B, int tid){
    int tx = tid & 15, ty = tid >> 4;
    int i0 = ty*8, j0 = tx*8;
    u64 acc[8][4];
    #pragma unroll
    for (int p = 0; p < 8; p++)
        #pragma unroll
        for (int q = 0; q < 4; q++) acc[p][q] = 0ull;
    #pragma unroll 2
    for (int m = 0; m < D_B; m++){
        float4 a0 = *(const float4*)&A[m*STR + i0];
        float4 a1 = *(const float4*)&A[m*STR + i0 + 4];
        F4U b0v, b1v;
        b0v.f = *(const float4*)&B[m*STR + j0];
        b1v.f = *(const float4*)&B[m*STR + j0 + 4];
        u64 bb[4] = { b0v.u[0], b0v.u[1], b1v.u[0], b1v.u[1] };
        float av[8] = { a0.x, a0.y, a0.z, a0.w, a1.x, a1.y, a1.z, a1.w };
        #pragma unroll
        for (int p = 0; p < 8; p++){
            u64 ap = bcast2(av[p]);
            #pragma unroll
            for (int q = 0; q < 4; q++) acc[p][q] = ffma2(ap, bb[q], acc[p][q]);
        }
    }
    #pragma unroll
    for (int p = 0; p < 8; p++){
        F4U o0, o1;
        o0.u[0] = acc[p][0]; o0.u[1] = acc[p][1];
        o1.u[0] = acc[p][2]; o1.u[1] = acc[p][3];
        *(float4*)&C[(i0+p)*STR + j0]     = o0.f;
        *(float4*)&C[(i0+p)*STR + j0 + 4] = o1.f;
    }
}

// C[i][j] = sum_m A[i][m] * B[m][j]        (A read along rows too, m-unroll 4)
__device__ __forceinline__ void mm_ab(float* __restrict__ C, const float* __restrict__ A,
                                      const float* __restrict__ B, int tid){
    int tx = tid & 15, ty = tid >> 4;
    int i0 = ty*8, j0 = tx*8;
    u64 acc[8][4];
    #pragma unroll
    for (int p = 0; p < 8; p++)
        #pragma unroll
        for (int q = 0; q < 4; q++) acc[p][q] = 0ull;
    for (int m = 0; m < D_B; m += 4){
        float4 a4[8];
        #pragma unroll
        for (int p = 0; p < 8; p++) a4[p] = *(const float4*)&A[(i0+p)*STR + m];
        #pragma unroll
        for (int s = 0; s < 4; s++){
            F4U b0v, b1v;
            b0v.f = *(const float4*)&B[(m+s)*STR + j0];
            b1v.f = *(const float4*)&B[(m+s)*STR + j0 + 4];
            u64 bb[4] = { b0v.u[0], b0v.u[1], b1v.u[0], b1v.u[1] };
            #pragma unroll
            for (int p = 0; p < 8; p++){
                float as = (s == 0) ? a4[p].x : (s == 1) ? a4[p].y
                         : (s == 2) ? a4[p].z : a4[p].w;
                u64 ap = bcast2(as);
                #pragma unroll
                for (int q = 0; q < 4; q++) acc[p][q] = ffma2(ap, bb[q], acc[p][q]);
            }
        }
    }
    #pragma unroll
    for (int p = 0; p < 8; p++){
        F4U o0, o1;
        o0.u[0] = acc[p][0]; o0.u[1] = acc[p][1];
        o1.u[0] = acc[p][2]; o1.u[1] = acc[p][3];
        *(float4*)&C[(i0+p)*STR + j0]     = o0.f;
        *(float4*)&C[(i0+p)*STR + j0 + 4] = o1.f;
    }
}

// out = inputs + lam * (A * B), streamed to gmem
__device__ __forceinline__ void mm_ab_out(const float* __restrict__ A, const float* __restrict__ B,
                                          const float* __restrict__ inp, float* __restrict__ out,
                                          float lam, int tid){
    int tx = tid & 15, ty = tid >> 4;
    int i0 = ty*8, j0 = tx*8;
    u64 acc[8][4];
    #pragma unroll
    for (int p = 0; p < 8; p++)
        #pragma unroll
        for (int q = 0; q < 4; q++) acc[p][q] = 0ull;
    for (int m = 0; m < D_B; m += 4){
        float4 a4[8];
        #pragma unroll
        for (int p = 0; p < 8; p++) a4[p] = *(const float4*)&A[(i0+p)*STR + m];
        #pragma unroll
        for (int s = 0; s < 4; s++){
            F4U b0v, b1v;
            b0v.f = *(const float4*)&B[(m+s)*STR + j0];
            b1v.f = *(const float4*)&B[(m+s)*STR + j0 + 4];
            u64 bb[4] = { b0v.u[0], b0v.u[1], b1v.u[0], b1v.u[1] };
            #pragma unroll
            for (int p = 0; p < 8; p++){
                float as = (s == 0) ? a4[p].x : (s == 1) ? a4[p].y
                         : (s == 2) ? a4[p].z : a4[p].w;
                u64 ap = bcast2(as);
                #pragma unroll
                for (int q = 0; q < 4; q++) acc[p][q] = ffma2(ap, bb[q], acc[p][q]);
            }
        }
    }
    #pragma unroll
    for (int p = 0; p < 8; p++){
        int row = i0 + p;
        float4 iv0 = *(const float4*)&inp[row*D_B + j0];
        float4 iv1 = *(const float4*)&inp[row*D_B + j0 + 4];
        float r[8];
        unpack2(acc[p][0], r[0], r[1]); unpack2(acc[p][1], r[2], r[3]);
        unpack2(acc[p][2], r[4], r[5]); unpack2(acc[p][3], r[6], r[7]);
        float4 o0 = make_float4(iv0.x + lam*r[0], iv0.y + lam*r[1],
                                iv0.z + lam*r[2], iv0.w + lam*r[3]);
        float4 o1 = make_float4(iv1.x + lam*r[4], iv1.y + lam*r[5],
                                iv1.z + lam*r[6], iv1.w + lam*r[7]);
        *(float4*)&out[row*D_B + j0]     = o0;
        *(float4*)&out[row*D_B + j0 + 4] = o1;
    }
}

// soft_pd_max, in place on smem tile M (stride STR). Ends synced.
__device__ __forceinline__ void soft_pd(float* M, int tid, float* s_dia,
                                        float* s_rinv, float* s_red){
    float mx = -3.4e38f;
    #pragma unroll
    for (int e = tid; e < MAT/4; e += TPB){
        int i = e >> 5, j = (e & 31) * 4;
        float4 v = *(const float4*)&M[i*STR + j];
        mx = fmaxf(mx, fmaxf(fmaxf(v.x, v.y), fmaxf(v.z, v.w)));
    }
    #pragma unroll
    for (int o = 16; o; o >>= 1) mx = fmaxf(mx, __shfl_xor_sync(0xffffffffu, mx, o));
    if ((tid & 31) == 0) s_red[tid >> 5] = mx;
    __syncthreads();
    if (tid == 0){
        float m2 = s_red[0];
        #pragma unroll
        for (int w = 1; w < TPB/32; w++) m2 = fmaxf(m2, s_red[w]);
        s_red[8] = m2;
    }
    __syncthreads();
    float bmax = s_red[8];
    #pragma unroll
    for (int e = tid; e < MAT/4; e += TPB){
        int i = e >> 5, j = (e & 31) * 4;
        float4 v = *(float4*)&M[i*STR + j];
        v.x = __expf(v.x - bmax); v.y = __expf(v.y - bmax);
        v.z = __expf(v.z - bmax); v.w = __expf(v.w - bmax);
        *(float4*)&M[i*STR + j] = v;
    }
    __syncthreads();
    if (tid < D_B){
        const float* r = M + tid*STR;
        float s = 0.f;
        #pragma unroll
        for (int j4 = 0; j4 < D_B/4; j4++){
            float4 v = *(const float4*)&r[j4*4];
            s += (v.x + v.y) + (v.z + v.w);
        }
        s_dia[tid] = s;
    }
    __syncthreads();
    if (tid < 32){
        float t = s_dia[tid] + s_dia[tid+32] + s_dia[tid+64] + s_dia[tid+96];
        #pragma unroll
        for (int o = 16; o; o >>= 1) t += __shfl_xor_sync(0xffffffffu, t, o);
        if (tid == 0) s_red[9] = t;
    }
    __syncthreads();
    if (tid < D_B){
        float total = s_red[9];
        float d = fmaxf(fmaxf(s_dia[tid], total / 100000.0f), 1e-5f);
        s_rinv[tid] = rsqrtf(d);
    }
    __syncthreads();
    #pragma unroll
    for (int e = tid; e < MAT/4; e += TPB){
        int i = e >> 5, j = (e & 31) * 4;
        float ri = s_rinv[i];
        float4 v = *(float4*)&M[i*STR + j];
        v.x *= ri * s_rinv[j];   v.y *= ri * s_rinv[j+1];
        v.z *= ri * s_rinv[j+2]; v.w *= ri * s_rinv[j+3];
        *(float4*)&M[i*STR + j] = v;
    }
    __syncthreads();
}

// ============================================================================
// Kernel 2: per-(n,k) chain. A_pre = K^T Q K; A = soft_pd(A_pre);
//           out = inputs + lam * (A X A^T)
// ============================================================================
__global__ __launch_bounds__(TPB, 1) void k_attn(const float* __restrict__ inp,
                                                 const float* __restrict__ lam,
                                                 float* __restrict__ out){
    extern __shared__ float sm[];
    float* b0 = sm;                 // XWK -> X -> A^T
    float* b1 = sm +     D_B*STR;   // XWQ -> A_pre -> A
    float* b2 = sm + 2 * D_B*STR;   // St  -> P = A*X
    __shared__ float s_dia[D_B], s_rinvd[D_B], s_rv[D_B], s_red[16];
    int tid = threadIdx.x;
    int nk  = blockIdx.x;
    size_t base = (size_t)nk * MAT;

    if (tid < D_B) s_rv[tid] = g_rv[nk*D_B + tid];
    load_tile(b0, g_XK + base, tid);
    load_tile(b1, g_XQ + base, tid);
    __syncthreads();
    mm_atb(b2, b1, b0, tid);        // St = Q^T K  (== (K^T Q)^T)
    __syncthreads();
    mm_atb(b1, b2, b0, tid);        // A_pre = St^T K = K^T Q K
    __syncthreads();
    load_X(b0, inp + base, s_rv, tid);        // overlap gmem X load with soft_pd
    soft_pd(b1, tid, s_dia, s_rinvd, s_red);  // b1 = A (ends synced)
    mm_ab(b2, b1, b0, tid);         // P = A X
    __syncthreads();
    for (int e = tid; e < MAT; e += TPB){     // b0 = A^T
        int i = e >> 7, j = e & 127;
        b0[j*STR + i] = b1[i*STR + j];
    }
    __syncthreads();
    mm_ab_out(b2, b0, inp + base, out + base, lam[nk & (C_B - 1)], tid);
}

// ============================================================================
extern "C" void kernel_launch(void* const* d_in, const int* in_sizes, int n_in,
                              void* d_out, int out_size){
    const float* inp = (const float*)d_in[0];
    const float* wq  = (const float*)d_in[1];
    const float* wk  = (const float*)d_in[2];
    const float* lam = (const float*)d_in[3];
    float* out = (float*)d_out;

    cudaFuncSetAttribute(k_attn, cudaFuncAttributeMaxDynamicSharedMemorySize, SMEM3);

    k_rinv<<<N_B*C_B, D_B>>>(inp);
    k_mix<<<dim3(D_B, N_B), 256>>>(inp, wq, wk);
    k_attn<<<N_B*C_B, TPB, SMEM3>>>(inp, lam, out);
}